// round 11
// baseline (speedup 1.0000x reference)
#include <cuda_runtime.h>
#include <cstdint>

#define NN 512
#define LUT_N 83521            // 17^4
#define NPIX (4 * NN * NN)

// ---------------- device scratch ----------------
__device__ float  g_q0f[3 * LUT_N];       // stage-0 quantized LUT (as float)
__device__ uint4  g_q1[3 * LUT_N];        // stage-1 quantized LUT (16 ch, biased u8, 16B/row)
__device__ float  g_x1[NPIX];             // stage-0 output image (integers 0..255)

__constant__ float c_samp0[108];
__constant__ float c_samp1[108];
__constant__ float c_sb0[12];
__constant__ float c_sb1[12];
__constant__ float c_resw[12];

// ---------------- f32x2 helpers ----------------
__device__ __forceinline__ unsigned long long pack2(unsigned lo, unsigned hi) {
    unsigned long long d;
    asm("mov.b64 %0, {%1, %2};" : "=l"(d) : "r"(lo), "r"(hi));
    return d;
}
__device__ __forceinline__ unsigned long long pack2f(float lo, float hi) {
    return pack2(__float_as_uint(lo), __float_as_uint(hi));
}
__device__ __forceinline__ void unpack2(unsigned long long v, float& lo, float& hi) {
    asm("mov.b64 {%0, %1}, %2;" : "=f"(lo), "=f"(hi) : "l"(v));
}
__device__ __forceinline__ unsigned long long fadd2(unsigned long long a, unsigned long long b) {
    unsigned long long d;
    asm("add.rn.f32x2 %0, %1, %2;" : "=l"(d) : "l"(a), "l"(b));
    return d;
}
__device__ __forceinline__ unsigned long long fsub2(unsigned long long a, unsigned long long b) {
    unsigned long long d;
    asm("sub.rn.f32x2 %0, %1, %2;" : "=l"(d) : "l"(a), "l"(b));
    return d;
}
__device__ __forceinline__ unsigned long long ffma2(unsigned long long a, unsigned long long b,
                                                    unsigned long long c) {
    unsigned long long d;
    asm("fma.rn.f32x2 %0, %1, %2, %3;" : "=l"(d) : "l"(a), "l"(b), "l"(c));
    return d;
}

// ---------------- LUT quantization ----------------
__global__ void quant_lut0(const float* __restrict__ src) {
    int i = blockIdx.x * blockDim.x + threadIdx.x;
    if (i < 3 * LUT_N) {
        float q = rintf(src[i] * 127.0f);
        g_q0f[i] = fminf(fmaxf(q, -127.0f), 127.0f);
    }
}

__device__ __forceinline__ unsigned q1_byte(float v) {
    float q = rintf(v * 127.0f);
    q = fminf(fmaxf(q, -127.0f), 127.0f);
    return (unsigned)((int)q + 128);   // biased u8
}

// word-per-thread: coalesced float4 reads, coalesced u32 writes
__global__ void quant_lut1(const float* __restrict__ src) {
    int i = blockIdx.x * blockDim.x + threadIdx.x;   // output word index
    if (i < 3 * LUT_N * 4) {
        float4 f = reinterpret_cast<const float4*>(src)[i];
        unsigned acc = q1_byte(f.x) | (q1_byte(f.y) << 8)
                     | (q1_byte(f.z) << 16) | (q1_byte(f.w) << 24);
        reinterpret_cast<unsigned*>(g_q1)[i] = acc;
    }
}

// ---------------- helpers ----------------
// Rotation-r tap position in the 5x5 neighborhood.
// r=0: X[p+u,q+v]; r=1: X[p+v,q-u]; r=2: X[p-u,q-v]; r=3: X[p-v,q+u]
__device__ __forceinline__ constexpr int nb_idx(int R, int u, int w) {
    int dy = (R == 0) ? u : (R == 1) ? w : (R == 2) ? -u : -w;
    int dx = (R == 0) ? w : (R == 1) ? -u : (R == 2) ? -w : u;
    return (2 + dy) * 5 + (2 + dx);
}

#define CSW(fa_, fb_, ta_, tb_)                         \
    { if (fa_ < fb_) { float tf = fa_; fa_ = fb_; fb_ = tf; \
                       int ti = ta_; ta_ = tb_; tb_ = ti; } }

// 4D simplex, standard weights (stage 0); ws pre-scaled by 1/16 (exact)
__device__ __forceinline__ void simplex_ws(const float v[4], int verts[5], float ws[5]) {
    int la = (int)(v[0] * 0.0625f), lb = (int)(v[1] * 0.0625f);
    int lc = (int)(v[2] * 0.0625f), ld = (int)(v[3] * 0.0625f);
    float f0 = v[0] - 16.0f * la, f1 = v[1] - 16.0f * lb;
    float f2 = v[2] - 16.0f * lc, f3 = v[3] - 16.0f * ld;
    int base = la * 4913 + lb * 289 + lc * 17 + ld;
    int t0 = 4913, t1 = 289, t2 = 17, t3 = 1;
    CSW(f0, f1, t0, t1); CSW(f2, f3, t2, t3);
    CSW(f0, f2, t0, t2); CSW(f1, f3, t1, t3);
    CSW(f1, f2, t1, t2);
    ws[0] = (16.0f - f0) * 0.0625f;
    ws[1] = (f0 - f1) * 0.0625f;
    ws[2] = (f1 - f2) * 0.0625f;
    ws[3] = (f2 - f3) * 0.0625f;
    ws[4] = f3 * 0.0625f;
    verts[0] = base;
    verts[1] = verts[0] + t0;
    verts[2] = verts[1] + t1;
    verts[3] = verts[2] + t2;
    verts[4] = verts[3] + t3;
}

// 4D simplex, telescoping weights (stage 1): gs[k] = f_sorted[k]/16
__device__ __forceinline__ void simplex_ts(const float v[4], int verts[5], float gs[4]) {
    int la = (int)(v[0] * 0.0625f), lb = (int)(v[1] * 0.0625f);
    int lc = (int)(v[2] * 0.0625f), ld = (int)(v[3] * 0.0625f);
    float f0 = v[0] - 16.0f * la, f1 = v[1] - 16.0f * lb;
    float f2 = v[2] - 16.0f * lc, f3 = v[3] - 16.0f * ld;
    int base = la * 4913 + lb * 289 + lc * 17 + ld;
    int t0 = 4913, t1 = 289, t2 = 17, t3 = 1;
    CSW(f0, f1, t0, t1); CSW(f2, f3, t2, t3);
    CSW(f0, f2, t0, t2); CSW(f1, f3, t1, t3);
    CSW(f1, f2, t1, t2);
    gs[0] = f0 * 0.0625f;
    gs[1] = f1 * 0.0625f;
    gs[2] = f2 * 0.0625f;
    gs[3] = f3 * 0.0625f;
    verts[0] = base;
    verts[1] = verts[0] + t0;
    verts[2] = verts[1] + t1;
    verts[3] = verts[2] + t2;
    verts[4] = verts[3] + t3;
}

// ---------------- stage 0 ----------------
__global__ void __launch_bounds__(256, 3) stage0_kernel(const float* __restrict__ x) {
    int q = blockIdx.x * 32 + threadIdx.x;
    int p = blockIdx.y * 8 + threadIdx.y;
    int b = blockIdx.z;

    unsigned long long pkA[9], pkB[9];   // (R0,R2) and (R1,R3) packed taps
    {
        const float* img = x + (size_t)b * NN * NN;
        float nb[25];
        int rr[5], cc[5];
#pragma unroll
        for (int i = 0; i < 5; i++) {
            rr[i] = min(max(p - 2 + i, 0), NN - 1);
            cc[i] = min(max(q - 2 + i, 0), NN - 1);
        }
#pragma unroll
        for (int i = 0; i < 5; i++)
#pragma unroll
            for (int j = 0; j < 5; j++)
                nb[i * 5 + j] = 255.0f * __ldg(img + rr[i] * NN + cc[j]);
#pragma unroll
        for (int u = 0; u < 3; u++)
#pragma unroll
            for (int w = 0; w < 3; w++) {
                int iA = nb_idx(0, u, w);
                int iB = nb_idx(1, u, w);
                pkA[u * 3 + w] = pack2f(nb[iA], nb[24 - iA]);
                pkB[u * 3 + w] = pack2f(nb[iB], nb[24 - iB]);
            }
    }

    float total = 0.0f;
#pragma unroll
    for (int s = 0; s < 3; s++) {
        const float* wg = c_samp0 + s * 36;
        const float* bi = c_sb0 + s * 4;
        const float* lt = g_q0f + s * LUT_N;

        float v[4][4];
#pragma unroll
        for (int ch = 0; ch < 4; ch++) {
            float bv = bi[ch];
            unsigned long long accA = pack2f(bv, bv);
            unsigned long long accB = accA;
#pragma unroll
            for (int t = 0; t < 9; t++) {
                float wv = wg[ch * 9 + t];
                unsigned long long w2 = pack2f(wv, wv);
                accA = ffma2(w2, pkA[t], accA);
                accB = ffma2(w2, pkB[t], accB);
            }
            unpack2(accA, v[0][ch], v[2][ch]);
            unpack2(accB, v[1][ch], v[3][ch]);
        }

        float acc = 0.0f;
#pragma unroll
        for (int R = 0; R < 4; R++) {
            int verts[5]; float ws[5];
            simplex_ws(v[R], verts, ws);
            float dot = 0.0f;
#pragma unroll
            for (int t = 0; t < 5; t++) dot += ws[t] * __ldg(lt + verts[t]);
            acc = rintf(acc + dot);
        }
        total += acc;
    }
    float o = rintf(fminf(fmaxf(total * (1.0f / 12.0f) + 127.0f, 0.0f), 255.0f));
    g_x1[(size_t)b * NN * NN + p * NN + q] = o;
}

// ---------------- stage 1 ----------------
// fused per-rotation: simplex + gather + telescoping accumulate;
// blk[k] += rintf(c[k]) (exact, order-free: every term integer-valued after rintf)
template <int R>
__device__ __forceinline__ void proc_rot1(const float v[4], const uint4* __restrict__ lt,
                                          float blk[16]) {
    int vt[5]; float gs[4];
    simplex_ts(v, vt, gs);

    uint4 d[5];
#pragma unroll
    for (int t = 0; t < 5; t++) d[t] = __ldg(lt + vt[t]);

    unsigned long long g2[4];
#pragma unroll
    for (int k = 0; k < 4; k++) {
        unsigned gb = __float_as_uint(gs[k]);
        g2[k] = pack2(gb, gb);
    }
    const unsigned long long B2 = pack2(0xCB000080u, 0xCB000080u);  // (-8388736,-8388736)

    float c[16];
#pragma unroll
    for (int pidx = 0; pidx < 8; pidx++) {
        const int kk = (pidx & 1) * 2;
        unsigned w0 = (pidx < 2) ? d[0].x : (pidx < 4) ? d[0].y : (pidx < 6) ? d[0].z : d[0].w;
        unsigned long long m_prev =
            pack2(__byte_perm(w0, 0x4B000000u, 0x7540u + kk),
                  __byte_perm(w0, 0x4B000000u, 0x7541u + kk));
        unsigned long long c2 = fadd2(m_prev, B2);   // exact: L0 per lane
#pragma unroll
        for (int t = 1; t < 5; t++) {
            unsigned wt = (pidx < 2) ? d[t].x : (pidx < 4) ? d[t].y
                        : (pidx < 6) ? d[t].z : d[t].w;
            unsigned long long m_cur =
                pack2(__byte_perm(wt, 0x4B000000u, 0x7540u + kk),
                      __byte_perm(wt, 0x4B000000u, 0x7541u + kk));
            // m_cur - m_prev exact (small integer diff); telescoping FMA
            c2 = ffma2(g2[t - 1], fsub2(m_cur, m_prev), c2);
            m_prev = m_cur;
        }
        unpack2(c2, c[2 * pidx], c[2 * pidx + 1]);
    }

#pragma unroll
    for (int i = 0; i < 4; i++)
#pragma unroll
        for (int j = 0; j < 4; j++) {
            int k = (R == 0) ? (i * 4 + j)
                  : (R == 1) ? ((3 - j) * 4 + i)
                  : (R == 2) ? ((3 - i) * 4 + (3 - j))
                             : (j * 4 + (3 - i));
            blk[i * 4 + j] += rintf(c[k]);
        }
}

__global__ void __launch_bounds__(256, 2) stage1_kernel(const float* __restrict__ x,
                                                        float* __restrict__ out) {
    int q = blockIdx.x * 32 + threadIdx.x;
    int p = blockIdx.y * 8 + threadIdx.y;
    int b = blockIdx.z;

    // packed neighborhood: lane0 = current image (g_x1), lane1 = prev image (255*x)
    unsigned long long pnb[25];
    {
        const float* img1 = g_x1 + (size_t)b * NN * NN;
        const float* img0 = x + (size_t)b * NN * NN;
        int rr[5], cc[5];
#pragma unroll
        for (int i = 0; i < 5; i++) {
            rr[i] = min(max(p - 2 + i, 0), NN - 1);
            cc[i] = min(max(q - 2 + i, 0), NN - 1);
        }
#pragma unroll
        for (int i = 0; i < 5; i++)
#pragma unroll
            for (int j = 0; j < 5; j++) {
                float v1 = __ldg(img1 + rr[i] * NN + cc[j]);
                float v0 = 255.0f * __ldg(img0 + rr[i] * NN + cc[j]);
                pnb[i * 5 + j] = pack2f(v1, v0);
            }
    }

    float blk[16];
#pragma unroll
    for (int k = 0; k < 16; k++) blk[k] = 0.0f;

#pragma unroll
    for (int s = 0; s < 3; s++) {
        const float* wg = c_samp1 + s * 36;
        const float* bi = c_sb1 + s * 4;
        const uint4* lt = g_q1 + s * LUT_N;

        // ---- paired conv (cur, prev share weights), W2 packs amortized over 4 rotations ----
        float v[4][4];   // [R][ch], blended
#pragma unroll
        for (int ch = 0; ch < 4; ch++) {
            unsigned long long W2[9];
#pragma unroll
            for (int t = 0; t < 9; t++) {
                float wv = wg[ch * 9 + t];
                W2[t] = pack2f(wv, wv);
            }
            float bv = bi[ch];
            unsigned long long B2b = pack2f(bv, bv);
            float rwc = fminf(fmaxf(c_resw[s * 4 + ch], 0.0f), 1.0f);
#pragma unroll
            for (int R = 0; R < 4; R++) {
                unsigned long long a2 = B2b;
#pragma unroll
                for (int u = 0; u < 3; u++)
#pragma unroll
                    for (int w = 0; w < 3; w++)
                        a2 = ffma2(W2[u * 3 + w], pnb[nb_idx(R, u, w)], a2);
                float vc, vp;
                unpack2(a2, vc, vp);
                v[R][ch] = vc + rwc * (vp - vc);
            }
        }

        proc_rot1<0>(v[0], lt, blk);
        proc_rot1<1>(v[1], lt, blk);
        proc_rot1<2>(v[2], lt, blk);
        proc_rot1<3>(v[3], lt, blk);
    }

    float* op = out + ((size_t)b << 22) + (size_t)(4 * p) * 2048 + 4 * q;
#pragma unroll
    for (int i = 0; i < 4; i++) {
        float4 o;
        o.x = rintf(fminf(fmaxf(blk[i * 4 + 0] * (1.0f / 3.0f), 0.0f), 255.0f)) * (1.0f / 255.0f);
        o.y = rintf(fminf(fmaxf(blk[i * 4 + 1] * (1.0f / 3.0f), 0.0f), 255.0f)) * (1.0f / 255.0f);
        o.z = rintf(fminf(fmaxf(blk[i * 4 + 2] * (1.0f / 3.0f), 0.0f), 255.0f)) * (1.0f / 255.0f);
        o.w = rintf(fminf(fmaxf(blk[i * 4 + 3] * (1.0f / 3.0f), 0.0f), 255.0f)) * (1.0f / 255.0f);
        *reinterpret_cast<float4*>(op + (size_t)i * 2048) = o;
    }
}

// ---------------- launch ----------------
extern "C" void kernel_launch(void* const* d_in, const int* in_sizes, int n_in,
                              void* d_out, int out_size) {
    const float* x     = (const float*)d_in[0];
    const float* lut0  = (const float*)d_in[1];
    const float* lut1  = (const float*)d_in[2];
    const float* samp0 = (const float*)d_in[3];
    const float* samp1 = (const float*)d_in[4];
    const float* sb0   = (const float*)d_in[5];
    const float* sb1   = (const float*)d_in[6];
    const float* resw  = (const float*)d_in[7];

    cudaMemcpyToSymbolAsync(c_samp0, samp0, 108 * sizeof(float), 0, cudaMemcpyDeviceToDevice);
    cudaMemcpyToSymbolAsync(c_samp1, samp1, 108 * sizeof(float), 0, cudaMemcpyDeviceToDevice);
    cudaMemcpyToSymbolAsync(c_sb0,   sb0,    12 * sizeof(float), 0, cudaMemcpyDeviceToDevice);
    cudaMemcpyToSymbolAsync(c_sb1,   sb1,    12 * sizeof(float), 0, cudaMemcpyDeviceToDevice);
    cudaMemcpyToSymbolAsync(c_resw,  resw,   12 * sizeof(float), 0, cudaMemcpyDeviceToDevice);

    quant_lut0<<<(3 * LUT_N + 255) / 256, 256>>>(lut0);
    quant_lut1<<<(3 * LUT_N * 4 + 255) / 256, 256>>>(lut1);

    dim3 blk0(32, 8, 1);
    dim3 grd0(NN / 32, NN / 8, 4);
    stage0_kernel<<<grd0, blk0>>>(x);

    dim3 blk1(32, 8, 1);
    dim3 grd1(NN / 32, NN / 8, 4);
    stage1_kernel<<<grd1, blk1>>>(x, (float*)d_out);
}